// round 15
// baseline (speedup 1.0000x reference)
#include <cuda_runtime.h>
#include <cstdint>

#define BATCH  8192
#define DCONT  1024
#define VCAT   10000
#define VEC    2500          // float4s per categorical row
#define FULL   0xffffffffu
#define NWARP  8             // warps per block (256 threads)
#define NCHUNK 20            // chunks of 128 vectors per row
#define CAP    640           // 20 ballots * 32 bits = hard max entries per row

__global__ void __launch_bounds__(256, 7)
spfl_kernel(const float* __restrict__ xcont,
            const float* __restrict__ xcat,
            const float* __restrict__ Wc,
            const float* __restrict__ Wcat,
            const float* __restrict__ bias,
            float* __restrict__ out) {
    __shared__ unsigned short lst[NWARP][CAP];   // 10 KB/block

    const int wid  = threadIdx.x >> 5;
    const int lane = threadIdx.x & 31;
    const int row  = blockIdx.x * NWARP + wid;   // 1 row per warp, exact grid
    const unsigned lt = (1u << lane) - 1u;

    const uint4*  __restrict__ xr    = reinterpret_cast<const uint4*>(xcat) + (size_t)row * VEC;
    const float4* __restrict__ Wcat4 = reinterpret_cast<const float4*>(Wcat);
    const float4* __restrict__ Wc4   = reinterpret_cast<const float4*>(Wc);

    // ===== Phase 1: minimal stream — 4 loads, OR-tree, ballot, rare append ==
    // No register prefetch pipeline: latency is hidden by ~55 warps/SM (TLP).
    int nE = 0;
    const uint4 z = make_uint4(0u, 0u, 0u, 0u);

    #pragma unroll 1
    for (int c = 0; c < NCHUNK; c++) {
        int b = c * 128 + lane;
        uint4 v0, v1, v2, v3;
        if (c < NCHUNK - 1) {
            v0 = __ldcs(xr + b);      v1 = __ldcs(xr + b + 32);
            v2 = __ldcs(xr + b + 64); v3 = __ldcs(xr + b + 96);
        } else {                               // tail chunk 19 (68 vectors)
            v0 = __ldcs(xr + b);               // 2432+lane < 2500 always
            v1 = __ldcs(xr + b + 32);          // 2464+lane < 2500 always
            v2 = (b + 64 < VEC) ? __ldcs(xr + b + 64) : z;   // lanes 0-3
            v3 = z;
        }
        unsigned o = ((v0.x | v0.y) | (v0.z | v0.w)) | ((v1.x | v1.y) | (v1.z | v1.w))
                   | ((v2.x | v2.y) | (v2.z | v2.w)) | ((v3.x | v3.y) | (v3.z | v3.w));
        unsigned bal = __ballot_sync(FULL, o != 0u);
        if (o) lst[wid][nE + __popc(bal & lt)] = (unsigned short)b;
        nE += __popc(bal);
    }

    __syncwarp();

    // ===== Phase 2: reload recorded groups, gather W_cat rows in parallel ===
    float a[16];
    #pragma unroll
    for (int k = 0; k < 16; k++) a[k] = 0.f;
    int cnt = 0;

    #pragma unroll 1
    for (int e = lane; e < nE; e += 32) {
        int idx = (int)lst[wid][e];            // vec index of segment 0
        #pragma unroll
        for (int k = 0; k < 4; k++) {          // the 4 recorded vectors
            int vi = idx + 32 * k;
            if (vi < VEC) {
                uint4 v = __ldg(xr + vi);
                unsigned mk = (v.x ? 1u : 0u) | (v.y ? 2u : 0u)
                            | (v.z ? 4u : 0u) | (v.w ? 8u : 0u);
                if (mk) {
                    cnt += __popc(mk);
                    int colb = vi * 4;
                    #pragma unroll
                    for (int j = 0; j < 4; j++) {
                        if (mk & (1u << j)) {
                            const float4* w = Wcat4 + (size_t)(colb + j) * 4;
                            float4 t0 = __ldg(w + 0), t1 = __ldg(w + 1);
                            float4 t2 = __ldg(w + 2), t3 = __ldg(w + 3);
                            a[0]+=t0.x;  a[1]+=t0.y;  a[2]+=t0.z;  a[3]+=t0.w;
                            a[4]+=t1.x;  a[5]+=t1.y;  a[6]+=t1.z;  a[7]+=t1.w;
                            a[8]+=t2.x;  a[9]+=t2.y;  a[10]+=t2.z; a[11]+=t2.w;
                            a[12]+=t3.x; a[13]+=t3.y; a[14]+=t3.z; a[15]+=t3.w;
                        }
                    }
                }
            }
        }
    }

    // Butterfly: full cat sums + count in every lane
    #pragma unroll
    for (int off = 16; off >= 1; off >>= 1) {
        #pragma unroll
        for (int k = 0; k < 16; k++) a[k] += __shfl_xor_sync(FULL, a[k], off);
        cnt += __shfl_xor_sync(FULL, cnt, off);
    }

    // Seed c/g-layout accumulator: lanes 0-3 hold one float4 quarter each
    const int g  = lane >> 2;
    const int c4 = lane & 3;
    float4 acc = make_float4(0.f, 0.f, 0.f, 0.f);
    if      (lane == 0) acc = make_float4(a[0],  a[1],  a[2],  a[3]);
    else if (lane == 1) acc = make_float4(a[4],  a[5],  a[6],  a[7]);
    else if (lane == 2) acc = make_float4(a[8],  a[9],  a[10], a[11]);
    else if (lane == 3) acc = make_float4(a[12], a[13], a[14], a[15]);

    // ===== Continuous branch: proven c/g layout (512B-contiguous W loads) ===
    const float* __restrict__ xc = xcont + (size_t)row * DCONT;
    #pragma unroll 1
    for (int jb = 0; jb < DCONT; jb += 32) {
        float x = __ldg(xc + jb + lane);
        #pragma unroll
        for (int s = 0; s < 4; s++) {
            int jl = s * 8 + g;
            float4 w = __ldg(Wc4 + (size_t)(jb + jl) * 4 + c4);
            float xv = __shfl_sync(FULL, x, jl);
            acc.x += xv * w.x; acc.y += xv * w.y;
            acc.z += xv * w.z; acc.w += xv * w.w;
        }
    }

    // Reduce cont partials over g (cat quarters ride along in g==0 lanes)
    #pragma unroll
    for (int off = 4; off <= 16; off <<= 1) {
        acc.x += __shfl_xor_sync(FULL, acc.x, off);
        acc.y += __shfl_xor_sync(FULL, acc.y, off);
        acc.z += __shfl_xor_sync(FULL, acc.z, off);
        acc.w += __shfl_xor_sync(FULL, acc.w, off);
    }

    if (lane < 4) {                              // g==0, quarter c4 == lane
        float4 b4 = __ldg(reinterpret_cast<const float4*>(bias) + lane);
        float f = (float)(DCONT + cnt);
        acc.x += f * b4.x; acc.y += f * b4.y;
        acc.z += f * b4.z; acc.w += f * b4.w;
        reinterpret_cast<float4*>(out)[(size_t)row * 4 + lane] = acc;
    }
}

extern "C" void kernel_launch(void* const* d_in, const int* in_sizes, int n_in,
                              void* d_out, int out_size) {
    const float* xcont = (const float*)d_in[0];   // [8192, 1024]
    const float* xcat  = (const float*)d_in[1];   // [8192, 10000]
    const float* Wc    = (const float*)d_in[2];   // [1024, 16]
    const float* Wcat  = (const float*)d_in[3];   // [10000, 16]
    const float* bias  = (const float*)d_in[4];   // [16]
    float* out = (float*)d_out;                   // [8192, 16]

    // 1 row per warp, 8 warps per block -> 1024 blocks (single wave, high occ)
    dim3 grid(BATCH / NWARP);
    dim3 block(32 * NWARP);
    spfl_kernel<<<grid, block>>>(xcont, xcat, Wc, Wcat, bias, out);
}